// round 15
// baseline (speedup 1.0000x reference)
#include <cuda_runtime.h>
#include <math.h>

// Problem constants (fixed by setup_inputs)
#define NN   50000
#define EE   800000
#define FF   128
#define HH   64
#define CC   16
#define KG   8          // gaussian kernels
#define SCAN_B 256
#define SCAN_NB ((NN + SCAN_B - 1) / SCAN_B)   // 196

// ---------------- scratch (static device globals; no allocation) -------------
// RULE (hard-won): NEVER pass these symbols as kernel arguments from host
// code. On GB300 (ATS) the host-shadow address silently aliases host memory.
// Reference them INSIDE kernel bodies only.
__device__ int   g_rows[EE];
__device__ int   g_cols[EE];
__device__ int   g_cnt[NN];      // in-degree (for mean)
__device__ int   g_rcnt[NN];     // out-degree histogram (for CSR)
__device__ int   g_pos[NN];      // scan output / scatter cursor -> row end
__device__ int   g_bsum[SCAN_NB];
__device__ int   g_boff[SCAN_NB];
__device__ int   g_srow[EE];     // row-sorted edge data (SoA)
__device__ int   g_scol[EE];
__device__ float g_sp0[EE];
__device__ float g_sp1[EE];
__device__ int   g_idx64;
__device__ float g_gx1[(size_t)NN * KG * HH];   // x @ g1_w    [N][512]
__device__ float g_r1 [(size_t)NN * HH];        // x @ root1_w [N][64]
__device__ float g_agg1[NN * HH];
__device__ float g_h[NN * HH];
__device__ float g_gx2[(size_t)NN * KG * CC];   // h @ g2_w    [N][128]
__device__ float g_agg2[NN * CC];

// ---------------- dtype detect ------------------------------------------------
__global__ void detect_kernel(const int* __restrict__ ei_words) {
    int allz = 1;
    for (int i = 0; i < 128; i++) {
        if (ei_words[2 * i + 1] != 0) { allz = 0; break; }
    }
    g_idx64 = allz;
}

// ---------------- zero accumulators ------------------------------------------
__global__ void zero_kernel(int N) {
    int i = blockIdx.x * blockDim.x + threadIdx.x;
    if (i < N * HH) g_agg1[i] = 0.f;
    if (i < N * CC) g_agg2[i] = 0.f;
    if (i < N) { g_cnt[i] = 0; g_rcnt[i] = 0; }
}

// ---------------- edge index normalization + degree counts -------------------
__global__ void convert_edges(const void* __restrict__ ei, int E) {
    int e = blockIdx.x * blockDim.x + threadIdx.x;
    if (e >= E) return;
    int r, c;
    if (g_idx64) {
        const long long* p = (const long long*)ei;
        r = (int)p[e];
        c = (int)p[(size_t)E + e];
    } else {
        const int* p = (const int*)ei;
        r = p[e];
        c = p[E + e];
    }
    g_rows[e] = r;
    g_cols[e] = c;
    atomicAdd(&g_cnt[c], 1);
    atomicAdd(&g_rcnt[r], 1);
}

// ---------------- multi-block exclusive scan of g_rcnt -> g_pos --------------
__global__ __launch_bounds__(SCAN_B) void scanA_kernel(int N) {
    __shared__ int sh[SCAN_B];
    int t = threadIdx.x;
    int i = blockIdx.x * SCAN_B + t;
    sh[t] = (i < N) ? g_rcnt[i] : 0;
    __syncthreads();
    for (int off = SCAN_B / 2; off > 0; off >>= 1) {
        if (t < off) sh[t] += sh[t + off];
        __syncthreads();
    }
    if (t == 0) g_bsum[blockIdx.x] = sh[0];
}
__global__ __launch_bounds__(SCAN_B) void scanB_kernel() {
    __shared__ int sh[SCAN_B];
    int t = threadIdx.x;
    sh[t] = (t < SCAN_NB) ? g_bsum[t] : 0;
    __syncthreads();
    for (int off = 1; off < SCAN_B; off <<= 1) {
        int v = (t >= off) ? sh[t - off] : 0;
        __syncthreads();
        sh[t] += v;
        __syncthreads();
    }
    if (t < SCAN_NB) g_boff[t] = sh[t] - g_bsum[t];   // exclusive
}
__global__ __launch_bounds__(SCAN_B) void scanC_kernel(int N) {
    __shared__ int sh[SCAN_B];
    int t = threadIdx.x;
    int i = blockIdx.x * SCAN_B + t;
    int own = (i < N) ? g_rcnt[i] : 0;
    sh[t] = own;
    __syncthreads();
    for (int off = 1; off < SCAN_B; off <<= 1) {
        int v = (t >= off) ? sh[t - off] : 0;
        __syncthreads();
        sh[t] += v;
        __syncthreads();
    }
    if (i < N) g_pos[i] = g_boff[blockIdx.x] + sh[t] - own;  // exclusive start
}

// ---------------- scatter edges into row-sorted SoA --------------------------
// After this kernel g_pos[r] == row end (start[r] = g_pos[r] - g_rcnt[r]).
__global__ void sort_kernel(const float* __restrict__ ea, int E) {
    int e = blockIdx.x * blockDim.x + threadIdx.x;
    if (e >= E) return;
    int r = g_rows[e], c = g_cols[e];
    int pos = atomicAdd(&g_pos[r], 1);
    g_srow[pos] = r;
    g_scol[pos] = c;
    g_sp0[pos] = ea[2 * (size_t)e];
    g_sp1[pos] = ea[2 * (size_t)e + 1];
}

// ---------------- GEMM A: BM=128, BN=64, BK=16, 8x4 microtile ----------------
// Used for r1 (N=64). MODE 1: A=Aarg(x), C=g_r1.
__global__ __launch_bounds__(256) void gemm_r1(const float* __restrict__ Aarg,
                                               const float* __restrict__ B,
                                               int M, int N, int K) {
    const float* A = Aarg;
    float* C = g_r1;

    const int bm = blockIdx.y * 128;
    const int bn = blockIdx.x * 64;
    __shared__ float sA[16][128];
    __shared__ float sB[16][64];
    const int t = threadIdx.x;
    const int mt = (t >> 4) << 3;
    const int nt = (t & 15) << 2;
    const int la_m = t >> 1;
    const int la_k = (t & 1) << 3;
    const int lb_k = t >> 4;
    const int lb_n = (t & 15) << 2;

    const bool arow_ok = (bm + la_m) < M;
    const float* Aptr = A + (size_t)(bm + la_m) * K + la_k;
    float acc[8][4] = {};

    for (int k0 = 0; k0 < K; k0 += 16) {
        float4 a4 = make_float4(0.f, 0.f, 0.f, 0.f);
        float4 a4b = make_float4(0.f, 0.f, 0.f, 0.f);
        if (arow_ok) {
            a4  = *(const float4*)(Aptr + k0);
            a4b = *(const float4*)(Aptr + k0 + 4);
        }
        sA[la_k + 0][la_m] = a4.x;
        sA[la_k + 1][la_m] = a4.y;
        sA[la_k + 2][la_m] = a4.z;
        sA[la_k + 3][la_m] = a4.w;
        sA[la_k + 4][la_m] = a4b.x;
        sA[la_k + 5][la_m] = a4b.y;
        sA[la_k + 6][la_m] = a4b.z;
        sA[la_k + 7][la_m] = a4b.w;
        *(float4*)&sB[lb_k][lb_n] =
            *(const float4*)(B + (size_t)(k0 + lb_k) * N + bn + lb_n);
        __syncthreads();
#pragma unroll
        for (int kk = 0; kk < 16; kk++) {
            float4 a_lo = *(const float4*)&sA[kk][mt];
            float4 a_hi = *(const float4*)&sA[kk][mt + 4];
            float4 b = *(const float4*)&sB[kk][nt];
            float ra[8] = {a_lo.x, a_lo.y, a_lo.z, a_lo.w,
                           a_hi.x, a_hi.y, a_hi.z, a_hi.w};
#pragma unroll
            for (int i = 0; i < 8; i++) {
                acc[i][0] += ra[i] * b.x;
                acc[i][1] += ra[i] * b.y;
                acc[i][2] += ra[i] * b.z;
                acc[i][3] += ra[i] * b.w;
            }
        }
        __syncthreads();
    }
#pragma unroll
    for (int i = 0; i < 8; i++) {
        int r = bm + mt + i;
        if (r < M) {
            float4 o = make_float4(acc[i][0], acc[i][1], acc[i][2], acc[i][3]);
            *(float4*)(C + (size_t)r * N + bn + nt) = o;
        }
    }
}

// ---------------- GEMM B: BM=128, BN=128, BK=16, 8x8 microtile ---------------
// 256 threads, 16KB smem, ~100 regs. 64 FFMA per 4 LDS.128 (1.0 B/FFMA).
// MODE 0: A=Aarg(x), C=g_gx1 (N=512,K=128). MODE 2: A=g_h, C=g_gx2 (N=128,K=64).
template <int MODE>
__global__ __launch_bounds__(256) void gemm_big(const float* __restrict__ Aarg,
                                                const float* __restrict__ B,
                                                int M, int N, int K) {
    const float* A = (MODE == 2) ? (const float*)g_h : Aarg;
    float* C = (MODE == 0) ? g_gx1 : g_gx2;

    const int bm = blockIdx.y * 128;
    const int bn = blockIdx.x * 128;
    __shared__ float sA[16][128];
    __shared__ float sB[16][128];
    const int t = threadIdx.x;
    const int mt = (t >> 4) << 3;        // 8-row sub-tile
    const int nt = (t & 15) << 3;        // 8-col sub-tile
    const int la_m = t >> 1;             // 0..127
    const int la_k = (t & 1) << 3;       // 0 or 8
    const int lb_k = t >> 4;             // 0..15
    const int lb_n = (t & 15) << 3;      // 0..120

    const bool arow_ok = (bm + la_m) < M;
    const float* Aptr = A + (size_t)(bm + la_m) * K + la_k;
    float acc[8][8] = {};

    for (int k0 = 0; k0 < K; k0 += 16) {
        float4 a4 = make_float4(0.f, 0.f, 0.f, 0.f);
        float4 a4b = make_float4(0.f, 0.f, 0.f, 0.f);
        if (arow_ok) {
            a4  = *(const float4*)(Aptr + k0);
            a4b = *(const float4*)(Aptr + k0 + 4);
        }
        sA[la_k + 0][la_m] = a4.x;
        sA[la_k + 1][la_m] = a4.y;
        sA[la_k + 2][la_m] = a4.z;
        sA[la_k + 3][la_m] = a4.w;
        sA[la_k + 4][la_m] = a4b.x;
        sA[la_k + 5][la_m] = a4b.y;
        sA[la_k + 6][la_m] = a4b.z;
        sA[la_k + 7][la_m] = a4b.w;
        const float* brow = B + (size_t)(k0 + lb_k) * N + bn + lb_n;
        *(float4*)&sB[lb_k][lb_n]     = *(const float4*)(brow);
        *(float4*)&sB[lb_k][lb_n + 4] = *(const float4*)(brow + 4);
        __syncthreads();
#pragma unroll
        for (int kk = 0; kk < 16; kk++) {
            float4 a_lo = *(const float4*)&sA[kk][mt];
            float4 a_hi = *(const float4*)&sA[kk][mt + 4];
            float4 b_lo = *(const float4*)&sB[kk][nt];
            float4 b_hi = *(const float4*)&sB[kk][nt + 4];
            float ra[8] = {a_lo.x, a_lo.y, a_lo.z, a_lo.w,
                           a_hi.x, a_hi.y, a_hi.z, a_hi.w};
            float rb[8] = {b_lo.x, b_lo.y, b_lo.z, b_lo.w,
                           b_hi.x, b_hi.y, b_hi.z, b_hi.w};
#pragma unroll
            for (int i = 0; i < 8; i++)
#pragma unroll
                for (int j = 0; j < 8; j++)
                    acc[i][j] += ra[i] * rb[j];
        }
        __syncthreads();
    }
#pragma unroll
    for (int i = 0; i < 8; i++) {
        int r = bm + mt + i;
        if (r < M) {
            float* crow = C + (size_t)r * N + bn + nt;
            *(float4*)(crow)     = make_float4(acc[i][0], acc[i][1], acc[i][2], acc[i][3]);
            *(float4*)(crow + 4) = make_float4(acc[i][4], acc[i][5], acc[i][6], acc[i][7]);
        }
    }
}

// ---------------- edge stage 1: WARP per SOURCE NODE (PROVEN R13) ------------
__global__ __launch_bounds__(256) void edge1_csr(const float* __restrict__ mu1,
                                                 const float* __restrict__ sig1,
                                                 int N) {
    int r = (blockIdx.x * blockDim.x + threadIdx.x) >> 5;
    int lane = threadIdx.x & 31;
    if (r >= N) return;
    int end = g_pos[r];
    int start = end - g_rcnt[r];
    if (start == end) return;

    const float2* gx = (const float2*)(g_gx1 + (size_t)r * (KG * HH));
    float2 v[KG];
#pragma unroll
    for (int k = 0; k < KG; k++) v[k] = gx[k * 32 + lane];

    float mx = 0.f, my = 0.f, ivx = 0.f, ivy = 0.f;
    if (lane < KG) {
        mx = mu1[lane * 2]; my = mu1[lane * 2 + 1];
        float sx = sig1[lane * 2], sy = sig1[lane * 2 + 1];
        ivx = 0.5f / (1e-15f + sx * sx);
        ivy = 0.5f / (1e-15f + sy * sy);
    }

    for (int e = start; e < end; e++) {
        float p0 = g_sp0[e];
        float p1 = g_sp1[e];
        int c = g_scol[e];
        float g = 0.f;
        if (lane < KG) {
            float dx = p0 - mx, dy = p1 - my;
            g = expf(-(dx * dx * ivx + dy * dy * ivy));
        }
        float ax = 0.f, ay = 0.f;
#pragma unroll
        for (int k = 0; k < KG; k++) {
            float gk = __shfl_sync(0xffffffffu, g, k);
            ax += gk * v[k].x;
            ay += gk * v[k].y;
        }
        float* dst = g_agg1 + (size_t)c * HH + 2 * lane;
        asm volatile("red.global.add.v2.f32 [%0], {%1, %2};" ::"l"(dst),
                     "f"(ax), "f"(ay) : "memory");
    }
}

// ---------------- node stage 1: mean + precomputed root + bias + elu ---------
__global__ void node1_kernel(const float* __restrict__ bias1, int N) {
    int i = blockIdx.x * blockDim.x + threadIdx.x;
    if (i >= N * HH) return;
    int n = i >> 6, o = i & 63;
    float cnt = fmaxf((float)g_cnt[n], 1.0f);
    float v = g_agg1[i] / cnt + g_r1[i] + bias1[o];
    g_h[i] = v > 0.f ? v : expm1f(v);
}

// ---------------- edge stage 2: 4 sorted edges per warp (PROVEN R13) ---------
__global__ __launch_bounds__(256) void edge2_kernel(const float* __restrict__ mu2,
                                                    const float* __restrict__ sig2,
                                                    int E) {
    int w = (blockIdx.x * blockDim.x + threadIdx.x) >> 5;
    int lane = threadIdx.x & 31;
    int sub = lane & 7, grp = lane >> 3;
    int e = w * 4 + grp;
    bool valid = (e < E);
    int r = 0, c = 0;
    float g = 0.f;
    if (valid) {
        r = g_srow[e];
        c = g_scol[e];
        float p0 = g_sp0[e];
        float p1 = g_sp1[e];
        float mx = mu2[sub * 2], my = mu2[sub * 2 + 1];
        float sx = sig2[sub * 2], sy = sig2[sub * 2 + 1];
        float dx = p0 - mx, dy = p1 - my;
        g = expf(-0.5f * (dx * dx / (1e-15f + sx * sx) +
                          dy * dy / (1e-15f + sy * sy)));
    }
    const float2* gx = (const float2*)(g_gx2 + (size_t)r * (KG * CC));
    float ax = 0.f, ay = 0.f;
#pragma unroll
    for (int k = 0; k < KG; k++) {
        float gk = __shfl_sync(0xffffffffu, g, (grp << 3) + k);
        if (valid) {
            float2 v = gx[k * 8 + sub];
            ax += gk * v.x;
            ay += gk * v.y;
        }
    }
    if (valid) {
        float* dst = g_agg2 + (size_t)c * CC + 2 * sub;
        asm volatile("red.global.add.v2.f32 [%0], {%1, %2};" ::"l"(dst),
                     "f"(ax), "f"(ay) : "memory");
    }
}

// ---------------- node stage 2: mean + inline root + bias + log_softmax ------
__global__ void node2_kernel(const float* __restrict__ root2,
                             const float* __restrict__ bias2,
                             float* __restrict__ out, int N) {
    int n = blockIdx.x * blockDim.x + threadIdx.x;
    if (n >= N) return;
    float cnt = fmaxf((float)g_cnt[n], 1.0f);
    float vals[CC];
    float m = -1e30f;
    for (int c = 0; c < CC; c++) {
        float root = 0.f;
        for (int f = 0; f < HH; f++)
            root += g_h[(size_t)n * HH + f] * root2[(size_t)f * CC + c];
        float v = g_agg2[(size_t)n * CC + c] / cnt + root + bias2[c];
        vals[c] = v;
        m = fmaxf(m, v);
    }
    float s = 0.f;
    for (int c = 0; c < CC; c++) s += expf(vals[c] - m);
    float lse = m + logf(s);
    for (int c = 0; c < CC; c++) out[(size_t)n * CC + c] = vals[c] - lse;
}

// ---------------- launch -----------------------------------------------------
extern "C" void kernel_launch(void* const* d_in, const int* in_sizes, int n_in,
                              void* d_out, int out_size) {
    const float* x      = (const float*)d_in[0];
    const void*  ei     = d_in[1];
    const float* ea     = (const float*)d_in[2];
    const float* g1_w   = (const float*)d_in[3];
    const float* mu1    = (const float*)d_in[4];
    const float* sig1   = (const float*)d_in[5];
    const float* root1  = (const float*)d_in[6];
    const float* bias1  = (const float*)d_in[7];
    const float* g2_w   = (const float*)d_in[8];
    const float* mu2    = (const float*)d_in[9];
    const float* sig2   = (const float*)d_in[10];
    const float* root2  = (const float*)d_in[11];
    const float* bias2  = (const float*)d_in[12];
    float* out = (float*)d_out;

    int N = in_sizes[0] / FF;       // 50000
    int E = in_sizes[2] / 2;        // 800000

    detect_kernel<<<1, 1>>>((const int*)ei);
    zero_kernel<<<(N * HH + 255) / 256, 256>>>(N);
    convert_edges<<<(E + 255) / 256, 256>>>(ei, E);
    scanA_kernel<<<SCAN_NB, SCAN_B>>>(N);
    scanB_kernel<<<1, SCAN_B>>>();
    scanC_kernel<<<SCAN_NB, SCAN_B>>>(N);
    sort_kernel<<<(E + 255) / 256, 256>>>(ea, E);

    int mb = (N + 127) / 128;       // 391

    // layer 1
    gemm_big<0><<<dim3(512 / 128, mb), 256>>>(x, g1_w, N, 512, FF);   // gx1
    gemm_r1<<<dim3(64 / 64, mb), 256>>>(x, root1, N, 64, FF);         // r1
    edge1_csr<<<(N + 7) / 8, 256>>>(mu1, sig1, N);
    node1_kernel<<<(N * HH + 255) / 256, 256>>>(bias1, N);

    // layer 2
    gemm_big<2><<<dim3(128 / 128, mb), 256>>>(nullptr, g2_w, N, 128, HH); // gx2
    edge2_kernel<<<(E / 4 + 7) / 8, 256>>>(mu2, sig2, E);
    node2_kernel<<<(N + 255) / 256, 256>>>(root2, bias2, out, N);
}

// round 16
// speedup vs baseline: 1.0694x; 1.0694x over previous
#include <cuda_runtime.h>
#include <math.h>

// Problem constants (fixed by setup_inputs)
#define NN   50000
#define EE   800000
#define FF   128
#define HH   64
#define CC   16
#define KG   8          // gaussian kernels
#define SCAN_B 256
#define SCAN_NB ((NN + SCAN_B - 1) / SCAN_B)   // 196

// ---------------- scratch (static device globals; no allocation) -------------
// RULE (hard-won): NEVER pass these symbols as kernel arguments from host
// code. On GB300 (ATS) the host-shadow address silently aliases host memory.
// Reference them INSIDE kernel bodies only.
__device__ int   g_rows[EE];
__device__ int   g_cols[EE];
__device__ int   g_cnt[NN];      // in-degree (for mean)
__device__ int   g_rcnt[NN];     // out-degree histogram (for CSR)
__device__ int   g_pos[NN];      // scan output / scatter cursor -> row end
__device__ int   g_bsum[SCAN_NB];
__device__ int   g_boff[SCAN_NB];
__device__ int   g_srow[EE];     // row-sorted edge data (SoA)
__device__ int   g_scol[EE];
__device__ float g_sp0[EE];
__device__ float g_sp1[EE];
__device__ int   g_idx64;
__device__ float g_gx1[(size_t)NN * KG * HH];   // x @ g1_w    [N][512]
__device__ float g_r1 [(size_t)NN * HH];        // x @ root1_w [N][64]
__device__ float g_agg1[NN * HH];
__device__ float g_h[NN * HH];
__device__ float g_gx2[(size_t)NN * KG * CC];   // h @ g2_w    [N][128]
__device__ float g_agg2[NN * CC];

// ---------------- dtype detect ------------------------------------------------
__global__ void detect_kernel(const int* __restrict__ ei_words) {
    int allz = 1;
    for (int i = 0; i < 128; i++) {
        if (ei_words[2 * i + 1] != 0) { allz = 0; break; }
    }
    g_idx64 = allz;
}

// ---------------- zero accumulators ------------------------------------------
__global__ void zero_kernel(int N) {
    int i = blockIdx.x * blockDim.x + threadIdx.x;
    if (i < N * HH) g_agg1[i] = 0.f;
    if (i < N * CC) g_agg2[i] = 0.f;
    if (i < N) { g_cnt[i] = 0; g_rcnt[i] = 0; }
}

// ---------------- edge index normalization + degree counts -------------------
__global__ void convert_edges(const void* __restrict__ ei, int E) {
    int e = blockIdx.x * blockDim.x + threadIdx.x;
    if (e >= E) return;
    int r, c;
    if (g_idx64) {
        const long long* p = (const long long*)ei;
        r = (int)p[e];
        c = (int)p[(size_t)E + e];
    } else {
        const int* p = (const int*)ei;
        r = p[e];
        c = p[E + e];
    }
    g_rows[e] = r;
    g_cols[e] = c;
    atomicAdd(&g_cnt[c], 1);
    atomicAdd(&g_rcnt[r], 1);
}

// ---------------- multi-block exclusive scan of g_rcnt -> g_pos --------------
__global__ __launch_bounds__(SCAN_B) void scanA_kernel(int N) {
    __shared__ int sh[SCAN_B];
    int t = threadIdx.x;
    int i = blockIdx.x * SCAN_B + t;
    sh[t] = (i < N) ? g_rcnt[i] : 0;
    __syncthreads();
    for (int off = SCAN_B / 2; off > 0; off >>= 1) {
        if (t < off) sh[t] += sh[t + off];
        __syncthreads();
    }
    if (t == 0) g_bsum[blockIdx.x] = sh[0];
}
__global__ __launch_bounds__(SCAN_B) void scanB_kernel() {
    __shared__ int sh[SCAN_B];
    int t = threadIdx.x;
    sh[t] = (t < SCAN_NB) ? g_bsum[t] : 0;
    __syncthreads();
    for (int off = 1; off < SCAN_B; off <<= 1) {
        int v = (t >= off) ? sh[t - off] : 0;
        __syncthreads();
        sh[t] += v;
        __syncthreads();
    }
    if (t < SCAN_NB) g_boff[t] = sh[t] - g_bsum[t];   // exclusive
}
__global__ __launch_bounds__(SCAN_B) void scanC_kernel(int N) {
    __shared__ int sh[SCAN_B];
    int t = threadIdx.x;
    int i = blockIdx.x * SCAN_B + t;
    int own = (i < N) ? g_rcnt[i] : 0;
    sh[t] = own;
    __syncthreads();
    for (int off = 1; off < SCAN_B; off <<= 1) {
        int v = (t >= off) ? sh[t - off] : 0;
        __syncthreads();
        sh[t] += v;
        __syncthreads();
    }
    if (i < N) g_pos[i] = g_boff[blockIdx.x] + sh[t] - own;  // exclusive start
}

// ---------------- scatter edges into row-sorted SoA --------------------------
// After this kernel g_pos[r] == row end (start[r] = g_pos[r] - g_rcnt[r]).
__global__ void sort_kernel(const float* __restrict__ ea, int E) {
    int e = blockIdx.x * blockDim.x + threadIdx.x;
    if (e >= E) return;
    int r = g_rows[e], c = g_cols[e];
    int pos = atomicAdd(&g_pos[r], 1);
    g_srow[pos] = r;
    g_scol[pos] = c;
    g_sp0[pos] = ea[2 * (size_t)e];
    g_sp1[pos] = ea[2 * (size_t)e + 1];
}

// ---------------- smem-tiled GEMM: C = A @ B, row-major (PROVEN R13) ---------
// BM=128, BN=64, BK=16, 256 threads, 8x4 microtile. MODE selects device-global
// operands IN-KERNEL (never via host args).
template <int MODE>
__global__ __launch_bounds__(256) void gemm_tile(const float* __restrict__ Aarg,
                                                 const float* __restrict__ B,
                                                 int M, int N, int K) {
    const float* A = (MODE == 2) ? (const float*)g_h : Aarg;
    float* C = (MODE == 0) ? g_gx1 : (MODE == 1) ? g_r1 : g_gx2;

    const int bm = blockIdx.y * 128;
    const int bn = blockIdx.x * 64;
    __shared__ float sA[16][128];
    __shared__ float sB[16][64];
    const int t = threadIdx.x;
    const int mt = (t >> 4) << 3;
    const int nt = (t & 15) << 2;
    const int la_m = t >> 1;
    const int la_k = (t & 1) << 3;
    const int lb_k = t >> 4;
    const int lb_n = (t & 15) << 2;

    const bool arow_ok = (bm + la_m) < M;
    const float* Aptr = A + (size_t)(bm + la_m) * K + la_k;
    float acc[8][4] = {};

    for (int k0 = 0; k0 < K; k0 += 16) {
        float4 a4 = make_float4(0.f, 0.f, 0.f, 0.f);
        float4 a4b = make_float4(0.f, 0.f, 0.f, 0.f);
        if (arow_ok) {
            a4  = *(const float4*)(Aptr + k0);
            a4b = *(const float4*)(Aptr + k0 + 4);
        }
        sA[la_k + 0][la_m] = a4.x;
        sA[la_k + 1][la_m] = a4.y;
        sA[la_k + 2][la_m] = a4.z;
        sA[la_k + 3][la_m] = a4.w;
        sA[la_k + 4][la_m] = a4b.x;
        sA[la_k + 5][la_m] = a4b.y;
        sA[la_k + 6][la_m] = a4b.z;
        sA[la_k + 7][la_m] = a4b.w;
        *(float4*)&sB[lb_k][lb_n] =
            *(const float4*)(B + (size_t)(k0 + lb_k) * N + bn + lb_n);
        __syncthreads();
#pragma unroll
        for (int kk = 0; kk < 16; kk++) {
            float4 a_lo = *(const float4*)&sA[kk][mt];
            float4 a_hi = *(const float4*)&sA[kk][mt + 4];
            float4 b = *(const float4*)&sB[kk][nt];
            float ra[8] = {a_lo.x, a_lo.y, a_lo.z, a_lo.w,
                           a_hi.x, a_hi.y, a_hi.z, a_hi.w};
#pragma unroll
            for (int i = 0; i < 8; i++) {
                acc[i][0] += ra[i] * b.x;
                acc[i][1] += ra[i] * b.y;
                acc[i][2] += ra[i] * b.z;
                acc[i][3] += ra[i] * b.w;
            }
        }
        __syncthreads();
    }
#pragma unroll
    for (int i = 0; i < 8; i++) {
        int r = bm + mt + i;
        if (r < M) {
            float4 o = make_float4(acc[i][0], acc[i][1], acc[i][2], acc[i][3]);
            *(float4*)(C + (size_t)r * N + bn + nt) = o;
        }
    }
}

// ---------------- edge stage 1: WARP per SOURCE NODE (PROVEN R13) ------------
__global__ __launch_bounds__(256) void edge1_csr(const float* __restrict__ mu1,
                                                 const float* __restrict__ sig1,
                                                 int N) {
    int r = (blockIdx.x * blockDim.x + threadIdx.x) >> 5;
    int lane = threadIdx.x & 31;
    if (r >= N) return;
    int end = g_pos[r];
    int start = end - g_rcnt[r];
    if (start == end) return;

    const float2* gx = (const float2*)(g_gx1 + (size_t)r * (KG * HH));
    float2 v[KG];
#pragma unroll
    for (int k = 0; k < KG; k++) v[k] = gx[k * 32 + lane];

    float mx = 0.f, my = 0.f, ivx = 0.f, ivy = 0.f;
    if (lane < KG) {
        mx = mu1[lane * 2]; my = mu1[lane * 2 + 1];
        float sx = sig1[lane * 2], sy = sig1[lane * 2 + 1];
        ivx = 0.5f / (1e-15f + sx * sx);
        ivy = 0.5f / (1e-15f + sy * sy);
    }

    for (int e = start; e < end; e++) {
        float p0 = g_sp0[e];
        float p1 = g_sp1[e];
        int c = g_scol[e];
        float g = 0.f;
        if (lane < KG) {
            float dx = p0 - mx, dy = p1 - my;
            g = expf(-(dx * dx * ivx + dy * dy * ivy));
        }
        float ax = 0.f, ay = 0.f;
#pragma unroll
        for (int k = 0; k < KG; k++) {
            float gk = __shfl_sync(0xffffffffu, g, k);
            ax += gk * v[k].x;
            ay += gk * v[k].y;
        }
        float* dst = g_agg1 + (size_t)c * HH + 2 * lane;
        asm volatile("red.global.add.v2.f32 [%0], {%1, %2};" ::"l"(dst),
                     "f"(ax), "f"(ay) : "memory");
    }
}

// ---------------- node stage 1: mean + precomputed root + bias + elu ---------
__global__ void node1_kernel(const float* __restrict__ bias1, int N) {
    int i = blockIdx.x * blockDim.x + threadIdx.x;
    if (i >= N * HH) return;
    int n = i >> 6, o = i & 63;
    float cnt = fmaxf((float)g_cnt[n], 1.0f);
    float v = g_agg1[i] / cnt + g_r1[i] + bias1[o];
    g_h[i] = v > 0.f ? v : expm1f(v);
}

// ---------------- edge stage 2: WARP per SOURCE NODE, 4 edges/iter -----------
// gx2 row register-cached once per node. Each 8-lane group serves one edge;
// lane sub owns features 2*sub, 2*sub+1 and computes gaussian sub for its
// group's edge (shfl within group).
__global__ __launch_bounds__(256) void edge2_csr(const float* __restrict__ mu2,
                                                 const float* __restrict__ sig2,
                                                 int N) {
    int r = (blockIdx.x * blockDim.x + threadIdx.x) >> 5;
    int lane = threadIdx.x & 31;
    if (r >= N) return;
    int end = g_pos[r];
    int start = end - g_rcnt[r];
    if (start == end) return;

    int sub = lane & 7, grp = lane >> 3;

    // cache row: each 8-lane group holds the full 128-float row (broadcast)
    const float2* gx = (const float2*)(g_gx2 + (size_t)r * (KG * CC));
    float2 v[KG];
#pragma unroll
    for (int k = 0; k < KG; k++) v[k] = gx[k * 8 + sub];

    float mx = mu2[sub * 2], my = mu2[sub * 2 + 1];
    float sx = sig2[sub * 2], sy = sig2[sub * 2 + 1];
    float ivx = 0.5f / (1e-15f + sx * sx);
    float ivy = 0.5f / (1e-15f + sy * sy);

    for (int e0 = start; e0 < end; e0 += 4) {
        int eh = e0 + grp;
        bool val = (eh < end);
        float g = 0.f;
        if (val) {
            float dx = g_sp0[eh] - mx, dy = g_sp1[eh] - my;
            g = expf(-(dx * dx * ivx + dy * dy * ivy));
        }
        float ax = 0.f, ay = 0.f;
#pragma unroll
        for (int k = 0; k < KG; k++) {
            float gk = __shfl_sync(0xffffffffu, g, (grp << 3) + k);
            ax += gk * v[k].x;
            ay += gk * v[k].y;
        }
        if (val) {
            int c = g_scol[eh];
            float* dst = g_agg2 + (size_t)c * CC + 2 * sub;
            asm volatile("red.global.add.v2.f32 [%0], {%1, %2};" ::"l"(dst),
                         "f"(ax), "f"(ay) : "memory");
        }
    }
}

// ---------------- node stage 2: mean + inline root + bias + log_softmax ------
__global__ void node2_kernel(const float* __restrict__ root2,
                             const float* __restrict__ bias2,
                             float* __restrict__ out, int N) {
    int n = blockIdx.x * blockDim.x + threadIdx.x;
    if (n >= N) return;
    float cnt = fmaxf((float)g_cnt[n], 1.0f);
    float vals[CC];
    float m = -1e30f;
    for (int c = 0; c < CC; c++) {
        float root = 0.f;
        for (int f = 0; f < HH; f++)
            root += g_h[(size_t)n * HH + f] * root2[(size_t)f * CC + c];
        float v = g_agg2[(size_t)n * CC + c] / cnt + root + bias2[c];
        vals[c] = v;
        m = fmaxf(m, v);
    }
    float s = 0.f;
    for (int c = 0; c < CC; c++) s += expf(vals[c] - m);
    float lse = m + logf(s);
    for (int c = 0; c < CC; c++) out[(size_t)n * CC + c] = vals[c] - lse;
}

// ---------------- launch -----------------------------------------------------
extern "C" void kernel_launch(void* const* d_in, const int* in_sizes, int n_in,
                              void* d_out, int out_size) {
    const float* x      = (const float*)d_in[0];
    const void*  ei     = d_in[1];
    const float* ea     = (const float*)d_in[2];
    const float* g1_w   = (const float*)d_in[3];
    const float* mu1    = (const float*)d_in[4];
    const float* sig1   = (const float*)d_in[5];
    const float* root1  = (const float*)d_in[6];
    const float* bias1  = (const float*)d_in[7];
    const float* g2_w   = (const float*)d_in[8];
    const float* mu2    = (const float*)d_in[9];
    const float* sig2   = (const float*)d_in[10];
    const float* root2  = (const float*)d_in[11];
    const float* bias2  = (const float*)d_in[12];
    float* out = (float*)d_out;

    int N = in_sizes[0] / FF;       // 50000
    int E = in_sizes[2] / 2;        // 800000
    int mb = (N + 127) / 128;       // 391

    // one-time side stream + events (created on the UNCAPTURED correctness
    // call, reused during graph capture -> standard fork/join capture pattern)
    static cudaStream_t s1 = nullptr;
    static cudaEvent_t evFork = nullptr, evGemm = nullptr;
    if (!s1) {
        cudaStreamCreateWithFlags(&s1, cudaStreamNonBlocking);
        cudaEventCreateWithFlags(&evFork, cudaEventDisableTiming);
        cudaEventCreateWithFlags(&evGemm, cudaEventDisableTiming);
    }

    // fork: gemm0 + r1 on s1, prep chain on the main stream
    cudaEventRecord(evFork, 0);
    cudaStreamWaitEvent(s1, evFork, 0);
    gemm_tile<0><<<dim3(512 / 64, mb), 256, 0, s1>>>(x, g1_w, N, 512, FF);
    gemm_tile<1><<<dim3(64 / 64, mb), 256, 0, s1>>>(x, root1, N, 64, FF);
    cudaEventRecord(evGemm, s1);

    detect_kernel<<<1, 1>>>((const int*)ei);
    zero_kernel<<<(N * HH + 255) / 256, 256>>>(N);
    convert_edges<<<(E + 255) / 256, 256>>>(ei, E);
    scanA_kernel<<<SCAN_NB, SCAN_B>>>(N);
    scanB_kernel<<<1, SCAN_B>>>();
    scanC_kernel<<<SCAN_NB, SCAN_B>>>(N);
    sort_kernel<<<(E + 255) / 256, 256>>>(ea, E);

    // join: edge1 needs sort (main) + gemm0/r1 (s1)
    cudaStreamWaitEvent(0, evGemm, 0);

    edge1_csr<<<(N + 7) / 8, 256>>>(mu1, sig1, N);
    node1_kernel<<<(N * HH + 255) / 256, 256>>>(bias1, N);

    // layer 2 (sequential dependency chain on main stream)
    gemm_tile<2><<<dim3(128 / 64, mb), 256>>>(nullptr, g2_w, N, 128, HH);
    edge2_csr<<<(N + 7) / 8, 256>>>(mu2, sig2, N);
    node2_kernel<<<(N + 255) / 256, 256>>>(root2, bias2, out, N);
}